// round 1
// baseline (speedup 1.0000x reference)
#include <cuda_runtime.h>
#include <math.h>

#define B_ROWS 8192
#define MCOLS  8199
#define MPAD   8320      // 65 * 128
#define H      128
#define EDIM   256
#define NCLS   7
#define NRT    64        // row tiles of 128
#define NCT    65        // col tiles of 128
#define TEMPC  0.07

__device__ float g_rn[MPAD * H];            // normalized rows (4.26 MB, L2 resident)
__device__ int   g_lab[MPAD];
__device__ int   g_ccount[NCLS];
__device__ float g_allp[NCT * B_ROWS];      // per-coltile partial: sum of e (diag & pad removed)
__device__ float g_matchp[NCT * B_ROWS];    // per-coltile partial: sum of e over label matches
__device__ float g_lv[B_ROWS];
__device__ float g_lm[B_ROWS];

// fast exp2 for t in [0, ~21]: round-to-nearest int via magic, deg-5 poly on [-0.5,0.5]
__device__ __forceinline__ float exp2fast(float t) {
    float kf = t + 12582912.0f;              // 1.5 * 2^23
    int   ki = __float_as_int(kf);
    float n  = kf - 12582912.0f;
    float r  = t - n;
    float p  = 0.0013333558f;
    p = fmaf(p, r, 0.0096181291f);
    p = fmaf(p, r, 0.0555041087f);
    p = fmaf(p, r, 0.2402265069f);
    p = fmaf(p, r, 0.6931471806f);
    p = fmaf(p, r, 1.0f);
    return p * __int_as_float((ki << 23) + 0x3f800000);
}

// ---------------- kernel Z: zero class-count histogram ----------------
__global__ void k_zero() {
    if (threadIdx.x < NCLS) g_ccount[threadIdx.x] = 0;
}

// ---------------- kernel A: fc(centers), normalize all rows, labels, histogram ----------------
__global__ void k_prep(const float* __restrict__ reps, const int* __restrict__ labels,
                       const float* __restrict__ centers, const float* __restrict__ fc_w,
                       const float* __restrict__ fc_b) {
    int bid = blockIdx.x;
    int t   = threadIdx.x;   // 0..127
    float x = 0.0f;
    int lab = -1;
    if (bid < B_ROWS) {
        x = reps[bid * H + t];
        lab = labels[bid];
    } else if (bid < MCOLS) {
        int c = bid - B_ROWS;
        float acc = fc_b[t];
        const float* cw = centers + c * EDIM;
        const float* w  = fc_w + t * EDIM;
        #pragma unroll 8
        for (int e = 0; e < EDIM; e++) acc = fmaf(cw[e], w[e], acc);
        x = acc;
        lab = c;
    }
    // block reduce sum of squares (128 threads)
    float s = x * x;
    #pragma unroll
    for (int o = 16; o; o >>= 1) s += __shfl_xor_sync(0xffffffffu, s, o);
    __shared__ float ws[4];
    int w = t >> 5, l = t & 31;
    if (l == 0) ws[w] = s;
    __syncthreads();
    float tot = ws[0] + ws[1] + ws[2] + ws[3];
    float inv = 1.0f / fmaxf(sqrtf(tot), 1e-8f);
    g_rn[bid * H + t] = x * inv;     // pad rows: x==0 -> writes 0
    if (t == 0) {
        g_lab[bid] = lab;
        if (bid < MCOLS) atomicAdd(&g_ccount[lab], 1);
    }
}

// ---------------- kernel B: fused cos-GEMM + exp + masked row sums ----------------
__global__ __launch_bounds__(256, 2) void k_main() {
    const int rt = blockIdx.x;       // row tile  (64)
    const int ct = blockIdx.y;       // col tile  (65)
    const int tid = threadIdx.x;
    const int tx = tid & 15;         // 0..15 -> 8 cols each
    const int ty = tid >> 4;         // 0..15 -> 8 rows each
    const int i0 = rt * 128;
    const int j0 = ct * 128;

    __shared__ float sA[32 * 128];   // k-major, XOR-swizzled groups
    __shared__ float sB[32 * 128];
    __shared__ int   sLI[128];
    __shared__ int   sLJ[128];

    if (tid < 128) sLI[tid] = g_lab[i0 + tid];
    else           sLJ[tid - 128] = g_lab[j0 + tid - 128];

    unsigned long long acc2[32];     // 4 row-pairs x 8 cols, packed f32x2
    #pragma unroll
    for (int q = 0; q < 32; q++) acc2[q] = 0ull;

    const float* Abase = g_rn + (size_t)i0 * H;
    const float* Bbase = g_rn + (size_t)j0 * H;
    const int lq = tid & 7;          // which k-quad within 32-k chunk
    const int lr = tid >> 3;         // 0..31 row within pass

    for (int kc = 0; kc < H; kc += 32) {
        float4 va[4], vb[4];
        #pragma unroll
        for (int p = 0; p < 4; p++) {
            int r = lr + p * 32;
            va[p] = *(const float4*)(Abase + r * H + kc + lq * 4);
            vb[p] = *(const float4*)(Bbase + r * H + kc + lq * 4);
        }
        __syncthreads();             // previous chunk's compute done
        #pragma unroll
        for (int p = 0; p < 4; p++) {
            int r = lr + p * 32;
            int off = ((((r >> 2) ^ lq) << 2) | (r & 3));   // fk for kk=4lq+c is lq
            sA[(lq * 4 + 0) * 128 + off] = va[p].x;
            sA[(lq * 4 + 1) * 128 + off] = va[p].y;
            sA[(lq * 4 + 2) * 128 + off] = va[p].z;
            sA[(lq * 4 + 3) * 128 + off] = va[p].w;
            sB[(lq * 4 + 0) * 128 + off] = vb[p].x;
            sB[(lq * 4 + 1) * 128 + off] = vb[p].y;
            sB[(lq * 4 + 2) * 128 + off] = vb[p].z;
            sB[(lq * 4 + 3) * 128 + off] = vb[p].w;
        }
        __syncthreads();

        #pragma unroll 8
        for (int k = 0; k < 32; k++) {
            const int fk = (k >> 2) & 7;
            const float* Ak = sA + k * 128;
            const float* Bk = sB + k * 128;
            ulonglong2 a0 = *(const ulonglong2*)(Ak + (((2 * ty + 0) ^ fk) << 2));
            ulonglong2 a1 = *(const ulonglong2*)(Ak + (((2 * ty + 1) ^ fk) << 2));
            float4 b0 = *(const float4*)(Bk + (((2 * tx + 0) ^ fk) << 2));
            float4 b1 = *(const float4*)(Bk + (((2 * tx + 1) ^ fk) << 2));
            unsigned long long ap[4];
            ap[0] = a0.x; ap[1] = a0.y; ap[2] = a1.x; ap[3] = a1.y;
            float bv[8];
            bv[0] = b0.x; bv[1] = b0.y; bv[2] = b0.z; bv[3] = b0.w;
            bv[4] = b1.x; bv[5] = b1.y; bv[6] = b1.z; bv[7] = b1.w;
            #pragma unroll
            for (int c = 0; c < 8; c++) {
                unsigned long long bd;
                asm("mov.b64 %0, {%1, %1};" : "=l"(bd) : "f"(bv[c]));
                #pragma unroll
                for (int rp = 0; rp < 4; rp++)
                    asm("fma.rn.f32x2 %0, %1, %2, %0;"
                        : "+l"(acc2[rp * 8 + c]) : "l"(ap[rp]), "l"(bd));
            }
        }
    }
    __syncthreads();

    // epilogue: e = exp(((1+cos)/2 + EPS)/TEMP)  ==  exp2(cos*C1 + C0)
    const float C1f = (float)(0.5 / TEMPC * 1.4426950408889634);
    const float C0f = (float)((0.5 + 1e-8) / TEMPC * 1.4426950408889634);
    const float e0  = exp2fast(C0f);     // value produced by a zero-vector pad column

    float sAllv[8], sMat[8];
    #pragma unroll
    for (int r = 0; r < 8; r++) { sAllv[r] = 0.0f; sMat[r] = 0.0f; }
    int li[8], lj[8];
    #pragma unroll
    for (int r = 0; r < 8; r++) li[r] = sLI[ty * 8 + r];
    #pragma unroll
    for (int c = 0; c < 8; c++) lj[c] = sLJ[tx * 8 + c];
    const bool diagB = (rt == ct);

    #pragma unroll
    for (int rp = 0; rp < 4; rp++) {
        #pragma unroll
        for (int c = 0; c < 8; c++) {
            float lo, hi;
            asm("mov.b64 {%0, %1}, %2;" : "=f"(lo), "=f"(hi) : "l"(acc2[rp * 8 + c]));
            {
                int r = 2 * rp;
                float e = exp2fast(fmaf(lo, C1f, C0f));
                if (diagB && (ty * 8 + r) == (tx * 8 + c)) e = 0.0f;
                sAllv[r] += e;
                if (li[r] == lj[c]) sMat[r] += e;
            }
            {
                int r = 2 * rp + 1;
                float e = exp2fast(fmaf(hi, C1f, C0f));
                if (diagB && (ty * 8 + r) == (tx * 8 + c)) e = 0.0f;
                sAllv[r] += e;
                if (li[r] == lj[c]) sMat[r] += e;
            }
        }
    }

    int npad = (j0 + 128) - MCOLS;
    if (npad < 0) npad = 0;
    float padAdj = (float)npad * e0;

    #pragma unroll
    for (int r = 0; r < 8; r++) {
        float a = sAllv[r], m = sMat[r];
        #pragma unroll
        for (int o = 1; o < 16; o <<= 1) {
            a += __shfl_xor_sync(0xffffffffu, a, o);
            m += __shfl_xor_sync(0xffffffffu, m, o);
        }
        if (tx == 0) {
            int row = i0 + ty * 8 + r;
            g_allp[ct * B_ROWS + row]   = a - padAdj;
            g_matchp[ct * B_ROWS + row] = m;
        }
    }
}

// ---------------- kernel C: per-row loss ----------------
__global__ void k_rows() {
    int i = blockIdx.x * 128 + threadIdx.x;   // grid 64 x 128 = 8192
    float all = 0.0f, match = 0.0f;
    #pragma unroll 5
    for (int ct = 0; ct < NCT; ct++) {
        all   += g_allp[ct * B_ROWS + i];
        match += g_matchp[ct * B_ROWS + i];
    }
    float pos = match;
    float neg = all - match;
    int lab = g_lab[i];
    float cnt = (float)(g_ccount[lab] - 1);
    float prob = pos / (pos + neg);
    prob = prob / (cnt + 1e-8f);
    float lv = -logf(prob + 1e-8f);
    bool msk = lv > 0.3f;
    g_lv[i] = msk ? lv : 0.0f;
    g_lm[i] = msk ? 1.0f : 0.0f;
}

// ---------------- kernel D: final reduction ----------------
__global__ void k_final(float* out) {
    int tid = threadIdx.x;    // 1024 threads
    float s = 0.0f, c = 0.0f;
    for (int i = tid; i < B_ROWS; i += 1024) { s += g_lv[i]; c += g_lm[i]; }
    #pragma unroll
    for (int o = 16; o; o >>= 1) {
        s += __shfl_xor_sync(0xffffffffu, s, o);
        c += __shfl_xor_sync(0xffffffffu, c, o);
    }
    __shared__ float ss[32], sc[32];
    int w = tid >> 5, l = tid & 31;
    if (l == 0) { ss[w] = s; sc[w] = c; }
    __syncthreads();
    if (w == 0) {
        s = ss[l]; c = sc[l];
        #pragma unroll
        for (int o = 16; o; o >>= 1) {
            s += __shfl_xor_sync(0xffffffffu, s, o);
            c += __shfl_xor_sync(0xffffffffu, c, o);
        }
        if (tid == 0) out[0] = s / (c + 1e-8f);
    }
}

extern "C" void kernel_launch(void* const* d_in, const int* in_sizes, int n_in,
                              void* d_out, int out_size) {
    const float* reps    = (const float*)d_in[0];
    const int*   labels  = (const int*)d_in[1];
    const float* centers = (const float*)d_in[2];
    const float* fc_w    = (const float*)d_in[3];
    const float* fc_b    = (const float*)d_in[4];
    float* out = (float*)d_out;

    k_zero<<<1, 32>>>();
    k_prep<<<MPAD, 128>>>(reps, labels, centers, fc_w, fc_b);
    dim3 g(NRT, NCT);
    k_main<<<g, 256>>>();
    k_rows<<<64, 128>>>();
    k_final<<<1, 1024>>>(out);
}